// round 14
// baseline (speedup 1.0000x reference)
#include <cuda_runtime.h>
#include <math.h>

// Problem constants
#define B_  64
#define T_  512
#define H_  1024
#define I_  1024
#define M_TOK (B_ * T_)

#define NBLK 128            // persistent blocks (1/SM, all co-resident)
#define NTHR 1024           // threads per persistent block (32 warps)
#define KCH  64             // k-slice per warp (16 warps per layer x 64 = 1024)
#define RS_STRIDE 17        // u64 stride for Rs rows (pad)

typedef unsigned long long u64t;

// ---------------------------------------------------------------------------
// Packed fp32x2 helpers (FFMA2: 2 fp32 MACs per instruction)
// ---------------------------------------------------------------------------
__device__ __forceinline__ u64t ffma2(u64t a, u64t b, u64t c)
{
    u64t d;
    asm("fma.rn.f32x2 %0, %1, %2, %3;" : "=l"(d) : "l"(a), "l"(b), "l"(c));
    return d;
}
__device__ __forceinline__ u64t fadd2(u64t a, u64t b)
{
    u64t d;
    asm("add.rn.f32x2 %0, %1, %2;" : "=l"(d) : "l"(a), "l"(b));
    return d;
}
__device__ __forceinline__ u64t splat2(float x)
{
    u64t d;
    unsigned r = __float_as_uint(x);
    asm("mov.b64 %0, {%1, %2};" : "=l"(d) : "r"(r), "r"(r));
    return d;
}
__device__ __forceinline__ u64t pack2(float lo, float hi)
{
    u64t d;
    unsigned a = __float_as_uint(lo), b = __float_as_uint(hi);
    asm("mov.b64 %0, {%1, %2};" : "=l"(d) : "r"(a), "r"(b));
    return d;
}
__device__ __forceinline__ float2 unpack2(u64t p)
{
    unsigned lo, hi;
    asm("mov.b64 {%0, %1}, %2;" : "=r"(lo), "=r"(hi) : "l"(p));
    return make_float2(__uint_as_float(lo), __uint_as_float(hi));
}
// L1-cached global load of a float2 (ld.global.ca). L1 coherence across ticks
// is guaranteed because the grid barrier's gpu-scope fence emits CCTL.IVALL.
__device__ __forceinline__ float2 ldca_f2(const float2* p)
{
    float2 v;
    asm volatile("ld.global.ca.v2.f32 {%0, %1}, [%2];"
                 : "=f"(v.x), "=f"(v.y) : "l"(p));
    return v;
}

// ---------------------------------------------------------------------------
// Scratch (__device__ globals; no allocation allowed)
// ---------------------------------------------------------------------------
__device__ float g_xw[M_TOK * H_];        // layer-0 input projection
__device__ float g_h0T[2][H_ * B_];       // layer-0 hidden, transposed h[k][b], ping-pong
__device__ float g_h1T[2][H_ * B_];       // layer-1 hidden, transposed
__device__ unsigned g_flags[NBLK * 32];   // barrier flags, 128B stride (zero-init)

// Distributed grid barrier: every block posts its flag, threads 0..127 poll
// all flags. Monotonic generations -> graph-replay safe. The gpu-scope fences
// also invalidate L1D (CCTL.IVALL), which is what makes L1-cached h reads
// coherent tick-to-tick.
__device__ __forceinline__ void grid_barrier(unsigned gen)
{
    __syncthreads();
    if (threadIdx.x == 0) {
        __threadfence();                                  // release prior stores
        *(volatile unsigned*)&g_flags[blockIdx.x * 32] = gen;
    }
    if (threadIdx.x < NBLK) {
        volatile unsigned* f = &g_flags[threadIdx.x * 32];
        while ((int)(*f - gen) < 0) { }
        __threadfence();                                  // acquire + L1D inval
    }
    __syncthreads();
}

// ---------------------------------------------------------------------------
// Input-projection GEMM (layer 0 only): C = X @ W_ih0^T + b_ih0 + b_hh0
// 128x128 tile, BK=16, 256 threads, 8x8/thread, FFMA2-packed over n.
// ---------------------------------------------------------------------------
__global__ __launch_bounds__(256) void gemm_bias_kernel(
    const float* __restrict__ A,
    const float* __restrict__ W,
    const float* __restrict__ b1,
    const float* __restrict__ b2,
    float* __restrict__ C,
    int M, int N, int K)
{
    __shared__ float As[16][128];
    __shared__ float Ws[16][128];

    const int m0 = blockIdx.y * 128;
    const int n0 = blockIdx.x * 128;
    const int tid = threadIdx.x;
    const int ty = tid >> 4;
    const int tx = tid & 15;

    const float* Ap = A + (size_t)m0 * K;
    const float* Wp = W + (size_t)n0 * K;

    const int f0  = tid;
    const int f1  = tid + 256;
    const int r0  = f0 >> 2, kq0 = (f0 & 3) * 4;
    const int r1  = f1 >> 2, kq1 = (f1 & 3) * 4;

    float4 pa0 = *(const float4*)(Ap + (size_t)r0 * K + kq0);
    float4 pa1 = *(const float4*)(Ap + (size_t)r1 * K + kq1);
    float4 pw0 = *(const float4*)(Wp + (size_t)r0 * K + kq0);
    float4 pw1 = *(const float4*)(Wp + (size_t)r1 * K + kq1);

    u64t acc2[8][4];
#pragma unroll
    for (int i = 0; i < 8; i++)
#pragma unroll
        for (int j = 0; j < 4; j++) acc2[i][j] = 0ull;

    for (int k0 = 0; k0 < K; k0 += 16) {
        As[kq0 + 0][r0] = pa0.x; As[kq0 + 1][r0] = pa0.y;
        As[kq0 + 2][r0] = pa0.z; As[kq0 + 3][r0] = pa0.w;
        As[kq1 + 0][r1] = pa1.x; As[kq1 + 1][r1] = pa1.y;
        As[kq1 + 2][r1] = pa1.z; As[kq1 + 3][r1] = pa1.w;
        Ws[kq0 + 0][r0] = pw0.x; Ws[kq0 + 1][r0] = pw0.y;
        Ws[kq0 + 2][r0] = pw0.z; Ws[kq0 + 3][r0] = pw0.w;
        Ws[kq1 + 0][r1] = pw1.x; Ws[kq1 + 1][r1] = pw1.y;
        Ws[kq1 + 2][r1] = pw1.z; Ws[kq1 + 3][r1] = pw1.w;
        __syncthreads();

        if (k0 + 16 < K) {
            int kn = k0 + 16;
            pa0 = *(const float4*)(Ap + (size_t)r0 * K + kn + kq0);
            pa1 = *(const float4*)(Ap + (size_t)r1 * K + kn + kq1);
            pw0 = *(const float4*)(Wp + (size_t)r0 * K + kn + kq0);
            pw1 = *(const float4*)(Wp + (size_t)r1 * K + kn + kq1);
        }

#pragma unroll
        for (int kk = 0; kk < 16; kk++) {
            float a[8];
            *(float4*)(a)     = *(const float4*)&As[kk][ty * 8];
            *(float4*)(a + 4) = *(const float4*)&As[kk][ty * 8 + 4];
            ulonglong2 wA = *(const ulonglong2*)&Ws[kk][tx * 8];
            ulonglong2 wB = *(const ulonglong2*)&Ws[kk][tx * 8 + 4];
            u64t w2[4] = { wA.x, wA.y, wB.x, wB.y };
#pragma unroll
            for (int i = 0; i < 8; i++) {
                u64t ap = splat2(a[i]);
#pragma unroll
                for (int j = 0; j < 4; j++)
                    acc2[i][j] = ffma2(ap, w2[j], acc2[i][j]);
            }
        }
        __syncthreads();
    }

    u64t bv2[4];
#pragma unroll
    for (int j = 0; j < 4; j++) {
        int n = n0 + tx * 8 + j * 2;
        bv2[j] = pack2(b1[n] + b2[n], b1[n + 1] + b2[n + 1]);
    }
#pragma unroll
    for (int i = 0; i < 8; i++) {
        int m = m0 + ty * 8 + i;
        float* cp = C + (size_t)m * N + n0 + tx * 8;
        ulonglong2 v0, v1;
        v0.x = fadd2(acc2[i][0], bv2[0]);
        v0.y = fadd2(acc2[i][1], bv2[1]);
        v1.x = fadd2(acc2[i][2], bv2[2]);
        v1.y = fadd2(acc2[i][3], bv2[3]);
        *(ulonglong2*)(cp)     = v0;
        *(ulonglong2*)(cp + 4) = v1;
    }
}

// ---------------------------------------------------------------------------
// Fused two-layer pipelined recurrence — layers split ACROSS warps, cohort-
// local named barriers, and L1-CACHED h-stream loads (the l1 cohort re-reads
// the xin lines the l0 cohort just pulled -> L1 hits instead of L2 trips;
// the per-tick gpu-scope fence flushes L1D so cross-tick reads stay coherent).
// 128 blocks x 1024 threads. Warps 0..15: layer-0 step u. Warps 16..31:
// layer-1 step u-1. One grid barrier per tick.
// ---------------------------------------------------------------------------
__global__ __launch_bounds__(NTHR, 1) void rnn_fused_pipelined(
    const float* __restrict__ Whh0,   // [H, H]
    const float* __restrict__ xw0,    // [B, T, H]
    const float* __restrict__ Wih1,   // [H, H]
    const float* __restrict__ Whh1,   // [H, H]
    const float* __restrict__ bih1,   // [H]
    const float* __restrict__ bhh1,   // [H]
    float* __restrict__ y,            // [B, T, H]
    float* __restrict__ hlast0,       // [B, H]
    float* __restrict__ hlast1)       // [B, H]
{
    extern __shared__ char smem[];
    u64t* W0  = (u64t*)smem;                  // [H_*4] l0 W_hh col-pairs
    u64t* Wi1 = W0  + H_ * 4;                 // [H_*4] l1 W_ih col-pairs
    u64t* Wh1 = Wi1 + H_ * 4;                 // [H_*4] l1 W_hh col-pairs
    u64t* Rs  = Wh1 + H_ * 4;                 // [512 * RS_STRIDE]

    const int tid  = threadIdx.x;
    const int warp = tid >> 5;       // 0..31
    const int l    = tid & 31;       // lane = 2 batch rows
    const int c0   = blockIdx.x * 8;
    const bool isL0 = (warp < 16);
    const int w    = warp & 15;      // k-slice index within cohort
    const int kbase = w * KCH;

    // ---- pack weight columns into smem once ----
    for (int idx = tid; idx < H_ * 4; idx += NTHR) {
        int k  = idx >> 2;
        int cp = idx & 3;
        int ca = c0 + 2 * cp, cb = ca + 1;
        W0 [idx] = pack2(Whh0[(size_t)ca * H_ + k], Whh0[(size_t)cb * H_ + k]);
        Wi1[idx] = pack2(Wih1[(size_t)ca * H_ + k], Wih1[(size_t)cb * H_ + k]);
        Wh1[idx] = pack2(Whh1[(size_t)ca * H_ + k], Whh1[(size_t)cb * H_ + k]);
    }

    // ---- zero hidden-state buffers ----
    {
        int g = blockIdx.x * 512 + (tid & 511);
        if (tid < 512) { g_h0T[0][g] = 0.0f; g_h0T[1][g] = 0.0f; }
        else           { g_h1T[0][g] = 0.0f; g_h1T[1][g] = 0.0f; }
    }

    // finalize mapping: fb = batch row, fcp = col pair
    const int fb  = tid & 63;
    const int fcp = (tid >> 6) & 3;
    const int cA  = c0 + fcp * 2;

    // layer-1 bias pair (used by finalize threads 512..767)
    const u64t b1p = pack2(bih1[cA] + bhh1[cA], bih1[cA + 1] + bhh1[cA + 1]);

    unsigned gen = *(volatile unsigned*)&g_flags[blockIdx.x * 32] + 1;
    grid_barrier(gen++);

    for (int u = 0; u <= T_; u++) {
        // xin = l0's input hidden = l1's input sequence (same buffer)
        const float2* xin  = (const float2*)g_h0T[u & 1];
        const float2* h1in = (const float2*)g_h1T[(u + 1) & 1];   // l1 h at t-1
        float* h0out = g_h0T[(u + 1) & 1];
        float* h1out = g_h1T[u & 1];

        if (isL0) {
            // ================= layer-0 cohort (warps 0..15) =================
            u64t xv = 0ull;
            if (tid < 256 && u < T_)
                xv = __ldcg((const u64t*)&xw0[((size_t)fb * T_ + u) * H_ + cA]);

            if (u < T_) {
                u64t a0[4] = {0,0,0,0}, a1[4] = {0,0,0,0};
#pragma unroll 8
                for (int i = 0; i < KCH; i++) {
                    int k = kbase + i;
                    float2 x2 = ldca_f2(&xin[k * 32 + l]);        // L1-cached
                    ulonglong2 wv0 = *(const ulonglong2*)&W0[k * 4];
                    ulonglong2 wv1 = *(const ulonglong2*)&W0[k * 4 + 2];
                    u64t p0 = splat2(x2.x);
                    u64t p1 = splat2(x2.y);
                    a0[0] = ffma2(p0, wv0.x, a0[0]); a0[1] = ffma2(p0, wv0.y, a0[1]);
                    a0[2] = ffma2(p0, wv1.x, a0[2]); a0[3] = ffma2(p0, wv1.y, a0[3]);
                    a1[0] = ffma2(p1, wv0.x, a1[0]); a1[1] = ffma2(p1, wv0.y, a1[1]);
                    a1[2] = ffma2(p1, wv1.x, a1[2]); a1[3] = ffma2(p1, wv1.y, a1[3]);
                }
                int bb0 = 2 * l, bb1 = 2 * l + 1;
#pragma unroll
                for (int cp = 0; cp < 4; cp++) {
                    Rs[(cp * 64 + bb0) * RS_STRIDE + w] = a0[cp];
                    Rs[(cp * 64 + bb1) * RS_STRIDE + w] = a1[cp];
                }
            }
            // cohort-local join (all 16 l0 warps)
            asm volatile("bar.sync 1, 512;" ::: "memory");

            if (tid < 256 && u < T_) {
                const u64t* row = &Rs[tid * RS_STRIDE];
                u64t s0 = fadd2(row[0],  row[1]);
                u64t s1 = fadd2(row[2],  row[3]);
                u64t s2 = fadd2(row[4],  row[5]);
                u64t s3 = fadd2(row[6],  row[7]);
                u64t s4 = fadd2(row[8],  row[9]);
                u64t s5 = fadd2(row[10], row[11]);
                u64t s6 = fadd2(row[12], row[13]);
                u64t s7 = fadd2(row[14], row[15]);
                u64t s = fadd2(fadd2(fadd2(s0, s1), fadd2(s2, s3)),
                               fadd2(fadd2(s4, s5), fadd2(s6, s7)));
                s = fadd2(s, xv);
                float2 sv = unpack2(s);
                float v0 = tanhf(sv.x);
                float v1 = tanhf(sv.y);
                h0out[(cA)     * 64 + fb] = v0;
                h0out[(cA + 1) * 64 + fb] = v1;
                if (u == T_ - 1)
                    *(u64t*)&hlast0[(size_t)fb * H_ + cA] = pack2(v0, v1);
            }
        } else {
            // ================= layer-1 cohort (warps 16..31, step t = u-1) =====
            if (u > 0) {
                u64t b0[4] = {0,0,0,0}, b1a[4] = {0,0,0,0};
#pragma unroll 4
                for (int i = 0; i < KCH; i++) {
                    int k = kbase + i;
                    float2 x2 = ldca_f2(&xin [k * 32 + l]);       // L1 hit (l0 pulled it)
                    float2 h2 = ldca_f2(&h1in[k * 32 + l]);       // L1-cached
                    ulonglong2 iv0 = *(const ulonglong2*)&Wi1[k * 4];
                    ulonglong2 iv1 = *(const ulonglong2*)&Wi1[k * 4 + 2];
                    ulonglong2 hv0 = *(const ulonglong2*)&Wh1[k * 4];
                    ulonglong2 hv1 = *(const ulonglong2*)&Wh1[k * 4 + 2];
                    u64t px0 = splat2(x2.x), px1 = splat2(x2.y);
                    u64t ph0 = splat2(h2.x), ph1 = splat2(h2.y);
                    b0[0]  = ffma2(px0, iv0.x, b0[0]);  b0[1]  = ffma2(px0, iv0.y, b0[1]);
                    b0[2]  = ffma2(px0, iv1.x, b0[2]);  b0[3]  = ffma2(px0, iv1.y, b0[3]);
                    b1a[0] = ffma2(px1, iv0.x, b1a[0]); b1a[1] = ffma2(px1, iv0.y, b1a[1]);
                    b1a[2] = ffma2(px1, iv1.x, b1a[2]); b1a[3] = ffma2(px1, iv1.y, b1a[3]);
                    b0[0]  = ffma2(ph0, hv0.x, b0[0]);  b0[1]  = ffma2(ph0, hv0.y, b0[1]);
                    b0[2]  = ffma2(ph0, hv1.x, b0[2]);  b0[3]  = ffma2(ph0, hv1.y, b0[3]);
                    b1a[0] = ffma2(ph1, hv0.x, b1a[0]); b1a[1] = ffma2(ph1, hv0.y, b1a[1]);
                    b1a[2] = ffma2(ph1, hv1.x, b1a[2]); b1a[3] = ffma2(ph1, hv1.y, b1a[3]);
                }
                int bb0 = 2 * l, bb1 = 2 * l + 1;
#pragma unroll
                for (int cp = 0; cp < 4; cp++) {
                    Rs[(256 + cp * 64 + bb0) * RS_STRIDE + w] = b0[cp];
                    Rs[(256 + cp * 64 + bb1) * RS_STRIDE + w] = b1a[cp];
                }
            }
            // cohort-local join (all 16 l1 warps)
            asm volatile("bar.sync 2, 512;" ::: "memory");

            if (tid < 768 && u > 0) {                 // threads 512..767
                int t = u - 1;
                const u64t* row = &Rs[(tid - 256) * RS_STRIDE];   // rows 256..511
                u64t s0 = fadd2(row[0],  row[1]);
                u64t s1 = fadd2(row[2],  row[3]);
                u64t s2 = fadd2(row[4],  row[5]);
                u64t s3 = fadd2(row[6],  row[7]);
                u64t s4 = fadd2(row[8],  row[9]);
                u64t s5 = fadd2(row[10], row[11]);
                u64t s6 = fadd2(row[12], row[13]);
                u64t s7 = fadd2(row[14], row[15]);
                u64t s = fadd2(fadd2(fadd2(s0, s1), fadd2(s2, s3)),
                               fadd2(fadd2(s4, s5), fadd2(s6, s7)));
                s = fadd2(s, b1p);
                float2 sv = unpack2(s);
                float v0 = tanhf(sv.x);
                float v1 = tanhf(sv.y);
                h1out[(cA)     * 64 + fb] = v0;
                h1out[(cA + 1) * 64 + fb] = v1;
                *(u64t*)&y[((size_t)fb * T_ + t) * H_ + cA] = pack2(v0, v1);
                if (t == T_ - 1)
                    *(u64t*)&hlast1[(size_t)fb * H_ + cA] = pack2(v0, v1);
            }
        }

        grid_barrier(gen++);
    }
}

// ---------------------------------------------------------------------------
// Launcher: 2 graph nodes.
// ---------------------------------------------------------------------------
extern "C" void kernel_launch(void* const* d_in, const int* in_sizes, int n_in,
                              void* d_out, int out_size)
{
    const float* X     = (const float*)d_in[0];
    const float* W_ih0 = (const float*)d_in[1];
    const float* b_ih0 = (const float*)d_in[2];
    const float* W_hh0 = (const float*)d_in[3];
    const float* b_hh0 = (const float*)d_in[4];
    const float* W_ih1 = (const float*)d_in[5];
    const float* b_ih1 = (const float*)d_in[6];
    const float* W_hh1 = (const float*)d_in[7];
    const float* b_hh1 = (const float*)d_in[8];

    float* out    = (float*)d_out;
    float* y_out  = out;                       // [B, T, H]
    float* h_last = out + (size_t)M_TOK * H_;  // [2, B, H]

    float* xw = nullptr;
    cudaGetSymbolAddress((void**)&xw, g_xw);

    const int rnn_smem = 3 * H_ * 4 * 8            // W0/Wi1/Wh1 96 KB
                       + 512 * RS_STRIDE * 8;      // Rs 69.6 KB
    static int attr_set = 0;
    if (!attr_set) {
        cudaFuncSetAttribute(rnn_fused_pipelined,
                             cudaFuncAttributeMaxDynamicSharedMemorySize, rnn_smem);
        attr_set = 1;
    }

    dim3 ggrid(H_ / 128, M_TOK / 128);   // (8, 256)

    gemm_bias_kernel<<<ggrid, 256>>>(X, W_ih0, b_ih0, b_hh0, xw, M_TOK, H_, I_);
    rnn_fused_pipelined<<<NBLK, NTHR, rnn_smem>>>(
        W_hh0, xw, W_ih1, W_hh1, b_ih1, b_hh1,
        y_out, h_last, h_last + B_ * H_);
}

// round 15
// speedup vs baseline: 1.0502x; 1.0502x over previous
#include <cuda_runtime.h>
#include <math.h>

// Problem constants
#define B_  64
#define T_  512
#define H_  1024
#define I_  1024
#define M_TOK (B_ * T_)

#define NBLK 128            // persistent blocks (1/SM, all co-resident)
#define NTHR 512            // threads per persistent block (16 warps)
#define KCH  64             // k-slice per warp per layer (16 warps x 64 = 1024)
#define RS_STRIDE 17        // u64 stride for Rs rows (pad)

typedef unsigned long long u64t;

// ---------------------------------------------------------------------------
// Packed fp32x2 helpers (FFMA2: 2 fp32 MACs per instruction)
// ---------------------------------------------------------------------------
__device__ __forceinline__ u64t ffma2(u64t a, u64t b, u64t c)
{
    u64t d;
    asm("fma.rn.f32x2 %0, %1, %2, %3;" : "=l"(d) : "l"(a), "l"(b), "l"(c));
    return d;
}
__device__ __forceinline__ u64t fadd2(u64t a, u64t b)
{
    u64t d;
    asm("add.rn.f32x2 %0, %1, %2;" : "=l"(d) : "l"(a), "l"(b));
    return d;
}
__device__ __forceinline__ u64t splat2(float x)
{
    u64t d;
    unsigned r = __float_as_uint(x);
    asm("mov.b64 %0, {%1, %2};" : "=l"(d) : "r"(r), "r"(r));
    return d;
}
__device__ __forceinline__ u64t pack2(float lo, float hi)
{
    u64t d;
    unsigned a = __float_as_uint(lo), b = __float_as_uint(hi);
    asm("mov.b64 %0, {%1, %2};" : "=l"(d) : "r"(a), "r"(b));
    return d;
}
__device__ __forceinline__ float2 unpack2(u64t p)
{
    unsigned lo, hi;
    asm("mov.b64 {%0, %1}, %2;" : "=r"(lo), "=r"(hi) : "l"(p));
    return make_float2(__uint_as_float(lo), __uint_as_float(hi));
}

// ---------------------------------------------------------------------------
// Scratch (__device__ globals; no allocation allowed)
// ---------------------------------------------------------------------------
__device__ float g_xw[M_TOK * H_];        // layer-0 input projection
__device__ float g_h0T[2][H_ * B_];       // layer-0 hidden, transposed h[k][b], ping-pong
__device__ float g_h1T[2][H_ * B_];       // layer-1 hidden, transposed
__device__ unsigned g_flags[NBLK * 32];   // barrier flags, 128B stride (zero-init)

// Distributed grid barrier: every block posts its flag, threads 0..127 poll
// all flags. Monotonic generations -> graph-replay safe.
__device__ __forceinline__ void grid_barrier(unsigned gen)
{
    __syncthreads();
    if (threadIdx.x == 0) {
        __threadfence();                                  // release prior stores
        *(volatile unsigned*)&g_flags[blockIdx.x * 32] = gen;
    }
    if (threadIdx.x < NBLK) {
        volatile unsigned* f = &g_flags[threadIdx.x * 32];
        while ((int)(*f - gen) < 0) { }
        __threadfence();                                  // acquire
    }
    __syncthreads();
}

// ---------------------------------------------------------------------------
// Input-projection GEMM (layer 0 only): C = X @ W_ih0^T + b_ih0 + b_hh0
// 128x128 tile, BK=16, 256 threads, 8x8/thread, FFMA2-packed over n.
// (proven round-11/13 version)
// ---------------------------------------------------------------------------
__global__ __launch_bounds__(256) void gemm_bias_kernel(
    const float* __restrict__ A,
    const float* __restrict__ W,
    const float* __restrict__ b1,
    const float* __restrict__ b2,
    float* __restrict__ C,
    int M, int N, int K)
{
    __shared__ float As[16][128];
    __shared__ float Ws[16][128];

    const int m0 = blockIdx.y * 128;
    const int n0 = blockIdx.x * 128;
    const int tid = threadIdx.x;
    const int ty = tid >> 4;
    const int tx = tid & 15;

    const float* Ap = A + (size_t)m0 * K;
    const float* Wp = W + (size_t)n0 * K;

    const int f0  = tid;
    const int f1  = tid + 256;
    const int r0  = f0 >> 2, kq0 = (f0 & 3) * 4;
    const int r1  = f1 >> 2, kq1 = (f1 & 3) * 4;

    float4 pa0 = *(const float4*)(Ap + (size_t)r0 * K + kq0);
    float4 pa1 = *(const float4*)(Ap + (size_t)r1 * K + kq1);
    float4 pw0 = *(const float4*)(Wp + (size_t)r0 * K + kq0);
    float4 pw1 = *(const float4*)(Wp + (size_t)r1 * K + kq1);

    u64t acc2[8][4];
#pragma unroll
    for (int i = 0; i < 8; i++)
#pragma unroll
        for (int j = 0; j < 4; j++) acc2[i][j] = 0ull;

    for (int k0 = 0; k0 < K; k0 += 16) {
        As[kq0 + 0][r0] = pa0.x; As[kq0 + 1][r0] = pa0.y;
        As[kq0 + 2][r0] = pa0.z; As[kq0 + 3][r0] = pa0.w;
        As[kq1 + 0][r1] = pa1.x; As[kq1 + 1][r1] = pa1.y;
        As[kq1 + 2][r1] = pa1.z; As[kq1 + 3][r1] = pa1.w;
        Ws[kq0 + 0][r0] = pw0.x; Ws[kq0 + 1][r0] = pw0.y;
        Ws[kq0 + 2][r0] = pw0.z; Ws[kq0 + 3][r0] = pw0.w;
        Ws[kq1 + 0][r1] = pw1.x; Ws[kq1 + 1][r1] = pw1.y;
        Ws[kq1 + 2][r1] = pw1.z; Ws[kq1 + 3][r1] = pw1.w;
        __syncthreads();

        if (k0 + 16 < K) {
            int kn = k0 + 16;
            pa0 = *(const float4*)(Ap + (size_t)r0 * K + kn + kq0);
            pa1 = *(const float4*)(Ap + (size_t)r1 * K + kn + kq1);
            pw0 = *(const float4*)(Wp + (size_t)r0 * K + kn + kq0);
            pw1 = *(const float4*)(Wp + (size_t)r1 * K + kn + kq1);
        }

#pragma unroll
        for (int kk = 0; kk < 16; kk++) {
            float a[8];
            *(float4*)(a)     = *(const float4*)&As[kk][ty * 8];
            *(float4*)(a + 4) = *(const float4*)&As[kk][ty * 8 + 4];
            ulonglong2 wA = *(const ulonglong2*)&Ws[kk][tx * 8];
            ulonglong2 wB = *(const ulonglong2*)&Ws[kk][tx * 8 + 4];
            u64t w2[4] = { wA.x, wA.y, wB.x, wB.y };
#pragma unroll
            for (int i = 0; i < 8; i++) {
                u64t ap = splat2(a[i]);
#pragma unroll
                for (int j = 0; j < 4; j++)
                    acc2[i][j] = ffma2(ap, w2[j], acc2[i][j]);
            }
        }
        __syncthreads();
    }

    u64t bv2[4];
#pragma unroll
    for (int j = 0; j < 4; j++) {
        int n = n0 + tx * 8 + j * 2;
        bv2[j] = pack2(b1[n] + b2[n], b1[n + 1] + b2[n + 1]);
    }
#pragma unroll
    for (int i = 0; i < 8; i++) {
        int m = m0 + ty * 8 + i;
        float* cp = C + (size_t)m * N + n0 + tx * 8;
        ulonglong2 v0, v1;
        v0.x = fadd2(acc2[i][0], bv2[0]);
        v0.y = fadd2(acc2[i][1], bv2[1]);
        v1.x = fadd2(acc2[i][2], bv2[2]);
        v1.y = fadd2(acc2[i][3], bv2[3]);
        *(ulonglong2*)(cp)     = v0;
        *(ulonglong2*)(cp + 4) = v1;
    }
}

// ---------------------------------------------------------------------------
// Fused two-layer pipelined recurrence — BALANCED SERIAL cohorts at 512
// threads. Every warp runs layer-0 (k-slice 64) then layer-1 (k-slice 64)
// serially within the tick: all 16 warps stay active the whole loop phase
// (uniform FFMA2 mix) and the 128-reg/thread budget lets ptxas front-batch
// the h-stream LDGs (MLP) instead of stalling on long scoreboard.
// One Rs dump per layer, ONE __syncthreads, 512 finalize threads, one grid
// barrier per tick. Block owns 8 output columns for both layers.
// ---------------------------------------------------------------------------
__global__ __launch_bounds__(NTHR, 1) void rnn_fused_pipelined(
    const float* __restrict__ Whh0,   // [H, H]
    const float* __restrict__ xw0,    // [B, T, H]
    const float* __restrict__ Wih1,   // [H, H]
    const float* __restrict__ Whh1,   // [H, H]
    const float* __restrict__ bih1,   // [H]
    const float* __restrict__ bhh1,   // [H]
    float* __restrict__ y,            // [B, T, H]
    float* __restrict__ hlast0,       // [B, H]
    float* __restrict__ hlast1)       // [B, H]
{
    extern __shared__ char smem[];
    u64t* W0  = (u64t*)smem;                  // [H_*4] l0 W_hh col-pairs (32 KB)
    u64t* Wi1 = W0  + H_ * 4;                 // [H_*4] l1 W_ih col-pairs
    u64t* Wh1 = Wi1 + H_ * 4;                 // [H_*4] l1 W_hh col-pairs
    u64t* Rs  = Wh1 + H_ * 4;                 // [512 * RS_STRIDE] (69.6 KB)

    const int tid  = threadIdx.x;
    const int w    = tid >> 5;       // warp id 0..15 = k-slice
    const int l    = tid & 31;       // lane = 2 batch rows
    const int c0   = blockIdx.x * 8;
    const int kbase = w * KCH;

    // ---- pack weight columns into smem once ----
    for (int idx = tid; idx < H_ * 4; idx += NTHR) {
        int k  = idx >> 2;
        int cp = idx & 3;
        int ca = c0 + 2 * cp, cb = ca + 1;
        W0 [idx] = pack2(Whh0[(size_t)ca * H_ + k], Whh0[(size_t)cb * H_ + k]);
        Wi1[idx] = pack2(Wih1[(size_t)ca * H_ + k], Wih1[(size_t)cb * H_ + k]);
        Wh1[idx] = pack2(Whh1[(size_t)ca * H_ + k], Whh1[(size_t)cb * H_ + k]);
    }

    // ---- zero initial hidden states (buffer 0): 128 blk x 512 thr = 64K ----
    {
        int g = blockIdx.x * NTHR + tid;
        g_h0T[0][g] = 0.0f;
        g_h1T[0][g] = 0.0f;
    }

    // finalize mapping: tid 0..255 -> l0 output row tid; tid 256..511 -> l1
    // output row tid (Rs rows 256..511). fb = batch row, fcp = col pair.
    const int fb  = tid & 63;
    const int fcp = (tid >> 6) & 3;
    const int cA  = c0 + fcp * 2;

    // layer-1 bias pair (used by finalize threads 256..511)
    const u64t b1p = pack2(bih1[cA] + bhh1[cA], bih1[cA + 1] + bhh1[cA + 1]);

    unsigned gen = *(volatile unsigned*)&g_flags[blockIdx.x * 32] + 1;
    grid_barrier(gen++);

    for (int u = 0; u <= T_; u++) {
        // xin = l0's input hidden = l1's input sequence (same buffer)
        const float2* xin  = (const float2*)g_h0T[u & 1];
        const float2* h1in = (const float2*)g_h1T[(u + 1) & 1];   // l1 h at t-1
        float* h0out = g_h0T[(u + 1) & 1];
        float* h1out = g_h1T[u & 1];

        // prefetch xw for l0 finalize (hides DRAM latency under the loops)
        u64t xv = 0ull;
        if (tid < 256 && u < T_)
            xv = __ldcg((const u64t*)&xw0[((size_t)fb * T_ + u) * H_ + cA]);

        // ================= layer-0 pass (this warp's k-slice) =================
        if (u < T_) {
            u64t a0[4] = {0,0,0,0}, a1[4] = {0,0,0,0};
#pragma unroll 8
            for (int i = 0; i < KCH; i++) {
                int k = kbase + i;
                float2 x2 = __ldcg(&xin[k * 32 + l]);
                ulonglong2 wv0 = *(const ulonglong2*)&W0[k * 4];
                ulonglong2 wv1 = *(const ulonglong2*)&W0[k * 4 + 2];
                u64t p0 = splat2(x2.x);
                u64t p1 = splat2(x2.y);
                a0[0] = ffma2(p0, wv0.x, a0[0]); a0[1] = ffma2(p0, wv0.y, a0[1]);
                a0[2] = ffma2(p0, wv1.x, a0[2]); a0[3] = ffma2(p0, wv1.y, a0[3]);
                a1[0] = ffma2(p1, wv0.x, a1[0]); a1[1] = ffma2(p1, wv0.y, a1[1]);
                a1[2] = ffma2(p1, wv1.x, a1[2]); a1[3] = ffma2(p1, wv1.y, a1[3]);
            }
            int bb0 = 2 * l, bb1 = 2 * l + 1;
#pragma unroll
            for (int cp = 0; cp < 4; cp++) {
                Rs[(cp * 64 + bb0) * RS_STRIDE + w] = a0[cp];
                Rs[(cp * 64 + bb1) * RS_STRIDE + w] = a1[cp];
            }
        }

        // ================= layer-1 pass (step t = u-1, same k-slice) ==========
        if (u > 0) {
            u64t b0[4] = {0,0,0,0}, b1a[4] = {0,0,0,0};
#pragma unroll 8
            for (int i = 0; i < KCH; i++) {
                int k = kbase + i;
                float2 x2 = __ldcg(&xin [k * 32 + l]);
                float2 h2 = __ldcg(&h1in[k * 32 + l]);
                ulonglong2 iv0 = *(const ulonglong2*)&Wi1[k * 4];
                ulonglong2 iv1 = *(const ulonglong2*)&Wi1[k * 4 + 2];
                ulonglong2 hv0 = *(const ulonglong2*)&Wh1[k * 4];
                ulonglong2 hv1 = *(const ulonglong2*)&Wh1[k * 4 + 2];
                u64t px0 = splat2(x2.x), px1 = splat2(x2.y);
                u64t ph0 = splat2(h2.x), ph1 = splat2(h2.y);
                b0[0]  = ffma2(px0, iv0.x, b0[0]);  b0[1]  = ffma2(px0, iv0.y, b0[1]);
                b0[2]  = ffma2(px0, iv1.x, b0[2]);  b0[3]  = ffma2(px0, iv1.y, b0[3]);
                b1a[0] = ffma2(px1, iv0.x, b1a[0]); b1a[1] = ffma2(px1, iv0.y, b1a[1]);
                b1a[2] = ffma2(px1, iv1.x, b1a[2]); b1a[3] = ffma2(px1, iv1.y, b1a[3]);
                b0[0]  = ffma2(ph0, hv0.x, b0[0]);  b0[1]  = ffma2(ph0, hv0.y, b0[1]);
                b0[2]  = ffma2(ph0, hv1.x, b0[2]);  b0[3]  = ffma2(ph0, hv1.y, b0[3]);
                b1a[0] = ffma2(ph1, hv0.x, b1a[0]); b1a[1] = ffma2(ph1, hv0.y, b1a[1]);
                b1a[2] = ffma2(ph1, hv1.x, b1a[2]); b1a[3] = ffma2(ph1, hv1.y, b1a[3]);
            }
            int bb0 = 2 * l, bb1 = 2 * l + 1;
#pragma unroll
            for (int cp = 0; cp < 4; cp++) {
                Rs[(256 + cp * 64 + bb0) * RS_STRIDE + w] = b0[cp];
                Rs[(256 + cp * 64 + bb1) * RS_STRIDE + w] = b1a[cp];
            }
        }

        __syncthreads();

        // ---- single finalize: 512 threads, one output row each ----
        {
            bool active = (tid < 256) ? (u < T_) : (u > 0);
            if (active) {
                const u64t* row = &Rs[tid * RS_STRIDE];
                u64t s0 = fadd2(row[0],  row[1]);
                u64t s1 = fadd2(row[2],  row[3]);
                u64t s2 = fadd2(row[4],  row[5]);
                u64t s3 = fadd2(row[6],  row[7]);
                u64t s4 = fadd2(row[8],  row[9]);
                u64t s5 = fadd2(row[10], row[11]);
                u64t s6 = fadd2(row[12], row[13]);
                u64t s7 = fadd2(row[14], row[15]);
                u64t s = fadd2(fadd2(fadd2(s0, s1), fadd2(s2, s3)),
                               fadd2(fadd2(s4, s5), fadd2(s6, s7)));
                if (tid < 256) {                      // layer-0 step u
                    s = fadd2(s, xv);
                    float2 sv = unpack2(s);
                    float v0 = tanhf(sv.x);
                    float v1 = tanhf(sv.y);
                    h0out[(cA)     * 64 + fb] = v0;
                    h0out[(cA + 1) * 64 + fb] = v1;
                    if (u == T_ - 1)
                        *(u64t*)&hlast0[(size_t)fb * H_ + cA] = pack2(v0, v1);
                } else {                              // layer-1 step t = u-1
                    int t = u - 1;
                    s = fadd2(s, b1p);
                    float2 sv = unpack2(s);
                    float v0 = tanhf(sv.x);
                    float v1 = tanhf(sv.y);
                    h1out[(cA)     * 64 + fb] = v0;
                    h1out[(cA + 1) * 64 + fb] = v1;
                    *(u64t*)&y[((size_t)fb * T_ + t) * H_ + cA] = pack2(v0, v1);
                    if (t == T_ - 1)
                        *(u64t*)&hlast1[(size_t)fb * H_ + cA] = pack2(v0, v1);
                }
            }
        }

        grid_barrier(gen++);
    }
}

// ---------------------------------------------------------------------------
// Launcher: 2 graph nodes.
// ---------------------------------------------------------------------------
extern "C" void kernel_launch(void* const* d_in, const int* in_sizes, int n_in,
                              void* d_out, int out_size)
{
    const float* X     = (const float*)d_in[0];
    const float* W_ih0 = (const float*)d_in[1];
    const float* b_ih0 = (const float*)d_in[2];
    const float* W_hh0 = (const float*)d_in[3];
    const float* b_hh0 = (const float*)d_in[4];
    const float* W_ih1 = (const float*)d_in[5];
    const float* b_ih1 = (const float*)d_in[6];
    const float* W_hh1 = (const float*)d_in[7];
    const float* b_hh1 = (const float*)d_in[8];

    float* out    = (float*)d_out;
    float* y_out  = out;                       // [B, T, H]
    float* h_last = out + (size_t)M_TOK * H_;  // [2, B, H]

    float* xw = nullptr;
    cudaGetSymbolAddress((void**)&xw, g_xw);

    const int rnn_smem = 3 * H_ * 4 * 8            // W0/Wi1/Wh1 96 KB
                       + 512 * RS_STRIDE * 8;      // Rs 69.6 KB
    static int attr_set = 0;
    if (!attr_set) {
        cudaFuncSetAttribute(rnn_fused_pipelined,
                             cudaFuncAttributeMaxDynamicSharedMemorySize, rnn_smem);
        attr_set = 1;
    }

    dim3 ggrid(H_ / 128, M_TOK / 128);   // (8, 256)

    gemm_bias_kernel<<<ggrid, 256>>>(X, W_ih0, b_ih0, b_hh0, xw, M_TOK, H_, I_);
    rnn_fused_pipelined<<<NBLK, NTHR, rnn_smem>>>(
        W_hh0, xw, W_ih1, W_hh1, b_ih1, b_hh1,
        y_out, h_last, h_last + B_ * H_);
}